// round 5
// baseline (speedup 1.0000x reference)
#include <cuda_runtime.h>
#include <cstdint>

#define NUSERS 100000
#define NITEMS 200000
#define NNODES 300000
#define DIM 64
#define ROWSTRIDE 256            // LEVELS * DIM
#define NNZ_E 1200000
#define NHOPS 3
#define INV_MESS_KEEP 1.1111112f // fp32(1/0.9)

#define SCAN_BLK 1024
#define NBLK ((NNODES + SCAN_BLK - 1) / SCAN_BLK)   // 293

// Scratch (__device__ globals; no allocations allowed). ~25 MB total.
__device__ unsigned g_deg[NNODES];        // degree histogram, then scatter cursor
__device__ unsigned g_rowptr[NNODES + 1]; // CSR row pointers
__device__ unsigned g_bsum[NBLK];         // scan block sums
__device__ unsigned g_eidx[NNZ_E];        // CSR pos -> original edge id (for RNG)
__device__ int      g_cols_csr[NNZ_E];    // CSR-ordered column ids
__device__ float    g_vals_csr[NNZ_E];    // CSR-ordered edge values
__device__ float2   g_ew[NNZ_E];          // per-hop packed {weight, bitcast(col)}

// ---------------------------------------------------------------------------
// Threefry-2x32 (JAX partitionable mode) — validated bit-exact (rel_err 7e-8)
// ---------------------------------------------------------------------------
__host__ __device__ __forceinline__ uint32_t rotl32(uint32_t x, int r) {
#ifdef __CUDA_ARCH__
    return __funnelshift_l(x, x, r);
#else
    return (x << r) | (x >> (32 - r));
#endif
}

__host__ __device__ __forceinline__ void threefry2x32(
    uint32_t k0, uint32_t k1, uint32_t x0, uint32_t x1,
    uint32_t& o0, uint32_t& o1)
{
    uint32_t ks2 = k0 ^ k1 ^ 0x1BD11BDAu;
    x0 += k0; x1 += k1;
#define TF_R(r) { x0 += x1; x1 = rotl32(x1, r); x1 ^= x0; }
    TF_R(13) TF_R(15) TF_R(26) TF_R(6)
    x0 += k1;  x1 += ks2 + 1u;
    TF_R(17) TF_R(29) TF_R(16) TF_R(24)
    x0 += ks2; x1 += k0 + 2u;
    TF_R(13) TF_R(15) TF_R(26) TF_R(6)
    x0 += k0;  x1 += k1 + 3u;
    TF_R(17) TF_R(29) TF_R(16) TF_R(24)
    x0 += k1;  x1 += ks2 + 4u;
    TF_R(13) TF_R(15) TF_R(26) TF_R(6)
    x0 += ks2; x1 += k0 + 5u;
#undef TF_R
    o0 = x0; o1 = x1;
}

__device__ __forceinline__ uint32_t tf_bits(uint32_t k0, uint32_t k1, uint32_t i) {
    uint32_t a, b;
    threefry2x32(k0, k1, 0u, i, a, b);
    return a ^ b;
}

__device__ __forceinline__ float bits_to_u01(uint32_t bits) {
    return __uint_as_float((bits >> 9) | 0x3f800000u) - 1.0f;
}

// ---------------------------------------------------------------------------
// CSR build: zero -> histogram -> 2-level exclusive scan -> scatter(+reorder)
// ---------------------------------------------------------------------------
__global__ void __launch_bounds__(256)
k_zero()
{
    unsigned i = blockIdx.x * blockDim.x + threadIdx.x;
    if (i < NNODES) g_deg[i] = 0u;
}

__global__ void __launch_bounds__(256)
k_hist(const int* __restrict__ rows)
{
    unsigned e = blockIdx.x * blockDim.x + threadIdx.x;
    if (e >= NNZ_E) return;
    atomicAdd(&g_deg[rows[e]], 1u);
}

// per-block exclusive scan over 1024 elems (256 threads x 4)
__global__ void __launch_bounds__(256)
k_scan1()
{
    __shared__ unsigned warp_sums[8];
    unsigned b = blockIdx.x;
    unsigned base = b * SCAN_BLK + threadIdx.x * 4u;
    unsigned v[4];
#pragma unroll
    for (int i = 0; i < 4; i++) {
        unsigned idx = base + i;
        v[i] = (idx < NNODES) ? g_deg[idx] : 0u;
    }
    unsigned tsum = v[0] + v[1] + v[2] + v[3];
    unsigned lane = threadIdx.x & 31u, wid = threadIdx.x >> 5;
    unsigned x = tsum;  // inclusive warp scan
#pragma unroll
    for (int o = 1; o < 32; o <<= 1) {
        unsigned y = __shfl_up_sync(0xFFFFFFFFu, x, o);
        if (lane >= (unsigned)o) x += y;
    }
    if (lane == 31) warp_sums[wid] = x;
    __syncthreads();
    if (wid == 0) {
        unsigned s = (lane < 8) ? warp_sums[lane] : 0u;
#pragma unroll
        for (int o = 1; o < 8; o <<= 1) {
            unsigned y = __shfl_up_sync(0xFFFFFFFFu, s, o);
            if (lane >= (unsigned)o) s += y;
        }
        if (lane < 8) warp_sums[lane] = s;  // inclusive over warps
    }
    __syncthreads();
    unsigned warp_off = (wid > 0) ? warp_sums[wid - 1] : 0u;
    unsigned run = warp_off + (x - tsum);   // thread-exclusive prefix
#pragma unroll
    for (int i = 0; i < 4; i++) {
        unsigned idx = base + i;
        if (idx < NNODES) g_rowptr[idx] = run;
        run += v[i];
    }
    if (threadIdx.x == 255) g_bsum[b] = warp_sums[7];  // block total
}

// single-block exclusive scan of block sums (NBLK = 293 <= 512)
__global__ void __launch_bounds__(512)
k_scan2()
{
    __shared__ unsigned sm[512];
    unsigned t = threadIdx.x;
    sm[t] = (t < NBLK) ? g_bsum[t] : 0u;
    __syncthreads();
#pragma unroll
    for (int o = 1; o < 512; o <<= 1) {
        unsigned y = (t >= (unsigned)o) ? sm[t - o] : 0u;
        __syncthreads();
        sm[t] += y;
        __syncthreads();
    }
    if (t < NBLK) g_bsum[t] = (t == 0) ? 0u : sm[t - 1];  // exclusive
}

__global__ void __launch_bounds__(256)
k_scan3()
{
    unsigned i = blockIdx.x * blockDim.x + threadIdx.x;
    if (i < NNODES) {
        g_rowptr[i] += g_bsum[i >> 10];
        g_deg[i] = 0u;                     // reuse as scatter cursor
    }
    if (i == 0) g_rowptr[NNODES] = NNZ_E;
}

// scatter + reorder edge payloads into CSR order
__global__ void __launch_bounds__(256)
k_scatter(const int* __restrict__ rows, const int* __restrict__ cols,
          const float* __restrict__ vals)
{
    unsigned e = blockIdx.x * blockDim.x + threadIdx.x;
    if (e >= NNZ_E) return;
    int r = rows[e];
    unsigned pos = g_rowptr[r] + atomicAdd(&g_deg[r], 1u);
    g_eidx[pos]     = e;
    g_cols_csr[pos] = cols[e];
    g_vals_csr[pos] = vals[e];
}

// ---------------------------------------------------------------------------
// Per-hop edge dropout, streaming in CSR order; packs {w, col} into 8 bytes.
// ---------------------------------------------------------------------------
__global__ void __launch_bounds__(256)
k_edge(uint32_t k0, uint32_t k1)
{
    unsigned p = blockIdx.x * blockDim.x + threadIdx.x;
    if (p >= NNZ_E) return;
    unsigned e = g_eidx[p];
    float u = bits_to_u01(tf_bits(k0, k1, e));
    float w = (u >= 0.5f) ? g_vals_csr[p] * 2.0f : 0.0f;
    g_ew[p] = make_float2(w, __int_as_float(g_cols_csr[p]));
}

// ---------------------------------------------------------------------------
// Fused SpMM + message dropout. TWO warps per row, float1 per lane (128B
// gathers). Edge payloads prefetched lane-parallel into smem, then the
// gather loop reads via LDS broadcast -> gathers are independent (high MLP).
// ---------------------------------------------------------------------------
template <bool HOP0>
__global__ void __launch_bounds__(256)
k_spmm_fused(const float* __restrict__ ue, const float* __restrict__ ie,
             float* __restrict__ out, int hop, uint32_t km0, uint32_t km1)
{
    __shared__ float2 stage[8][32];            // per-warp edge staging

    unsigned gw = blockIdx.x * 8u + (threadIdx.x >> 5);  // global warp
    unsigned r = gw >> 1;                      // row
    if (r >= NNODES) return;
    unsigned half = gw & 1u;                   // which 32 floats of the row
    unsigned lane = threadIdx.x & 31u;
    unsigned wid  = threadIdx.x >> 5;

    unsigned start = g_rowptr[r];
    unsigned end   = g_rowptr[r + 1];

    float acc = 0.f;
    unsigned dcol = half * 32u + lane;         // element within the 64-row
    const float* src_base = out + (size_t)hop * DIM + dcol;  // when !HOP0

    for (unsigned base = start; base < end; base += 32u) {
        unsigned n = min(32u, end - base);
        if (lane < n) stage[wid][lane] = g_ew[base + lane];  // coalesced
        __syncwarp();
#pragma unroll 4
        for (unsigned i = 0; i < n; i++) {
            float2 ew = stage[wid][i];         // LDS broadcast
            if (ew.x != 0.0f) {
                int c = __float_as_int(ew.y);
                float s;
                if (HOP0)
                    s = (c < NUSERS) ? ue[(size_t)c * DIM + dcol]
                                     : ie[(size_t)(c - NUSERS) * DIM + dcol];
                else
                    s = src_base[(size_t)c * ROWSTRIDE];
                acc += ew.x * s;
            }
        }
        __syncwarp();
    }

    // message dropout epilogue: element j = r*64 + dcol (one cipher/lane)
    unsigned j = r * 64u + dcol;
    float u = bits_to_u01(tf_bits(km0, km1, j));
    float res = (u < 0.9f) ? acc * INV_MESS_KEEP : 0.0f;

    float* orow = out + (size_t)r * ROWSTRIDE;
    orow[(size_t)(hop + 1) * DIM + dcol] = res;

    if (HOP0) {
        // emit level-0 copy (row r of concat(ue, ie))
        float e0 = (r < NUSERS) ? ue[(size_t)r * DIM + dcol]
                                : ie[(size_t)(r - NUSERS) * DIM + dcol];
        orow[dcol] = e0;
    }
}

// ---------------------------------------------------------------------------
// Launch
// ---------------------------------------------------------------------------
extern "C" void kernel_launch(void* const* d_in, const int* in_sizes, int n_in,
                              void* d_out, int out_size)
{
    const float* ue = nullptr; const float* ie = nullptr;
    const float* vals = nullptr; const int* rows = nullptr; const int* cols = nullptr;
    int nnz_seen = 0;
    for (int i = 0; i < n_in; i++) {
        if (in_sizes[i] == NUSERS * DIM)      ue = (const float*)d_in[i];
        else if (in_sizes[i] == NITEMS * DIM) ie = (const float*)d_in[i];
        else if (in_sizes[i] == NNZ_E) {
            if (nnz_seen == 0)      vals = (const float*)d_in[i];
            else if (nnz_seen == 1) rows = (const int*)d_in[i];
            else                    cols = (const int*)d_in[i];
            nnz_seen++;
        }
    }
    float* out = (float*)d_out;

    // JAX key derivation (validated): base=(0,42); hk=cipher(base,(0,hop));
    // ke=cipher(hk,(0,0)), km=cipher(hk,(0,1))
    uint32_t ke0[NHOPS], ke1[NHOPS], km0[NHOPS], km1[NHOPS];
    for (int h = 0; h < NHOPS; h++) {
        uint32_t h0, h1;
        threefry2x32(0u, 42u, 0u, (uint32_t)h, h0, h1);
        threefry2x32(h0, h1, 0u, 0u, ke0[h], ke1[h]);
        threefry2x32(h0, h1, 0u, 1u, km0[h], km1[h]);
    }

    const int TB = 256;
    unsigned gb_node = (NNODES + TB - 1) / TB;
    unsigned gb_edge = (NNZ_E + TB - 1) / TB;
    unsigned gb_fuse = ((unsigned)NNODES * 2u + 7u) / 8u;   // 2 warps/row, 8 warps/block

    k_zero<<<gb_node, TB>>>();
    k_hist<<<gb_edge, TB>>>(rows);
    k_scan1<<<NBLK, TB>>>();
    k_scan2<<<1, 512>>>();
    k_scan3<<<gb_node, TB>>>();
    k_scatter<<<gb_edge, TB>>>(rows, cols, vals);

    for (int h = 0; h < NHOPS; h++) {
        k_edge<<<gb_edge, TB>>>(ke0[h], ke1[h]);
        if (h == 0)
            k_spmm_fused<true><<<gb_fuse, TB>>>(ue, ie, out, h, km0[h], km1[h]);
        else
            k_spmm_fused<false><<<gb_fuse, TB>>>(ue, ie, out, h, km0[h], km1[h]);
    }
}

// round 6
// speedup vs baseline: 1.5633x; 1.5633x over previous
#include <cuda_runtime.h>
#include <cstdint>

#define NUSERS 100000
#define NITEMS 200000
#define NNODES 300000
#define DIM 64
#define ROWSTRIDE 256            // LEVELS * DIM
#define NNZ_E 1200000
#define NHOPS 3
#define INV_MESS_KEEP 1.1111112f // fp32(1/0.9)

#define SCAN_BLK 1024
#define NBLK ((NNODES + SCAN_BLK - 1) / SCAN_BLK)   // 293

// Scratch (__device__ globals; no allocations allowed). ~21 MB total.
__device__ unsigned g_deg[NNODES];        // degree histogram, then scatter cursor
__device__ unsigned g_rowptr[NNODES + 1]; // CSR row pointers
__device__ unsigned g_bsum[NBLK];         // scan block sums
__device__ float4   g_ew3[NNZ_E];         // CSR-ordered {w_hop0, w_hop1, w_hop2, bitcast(col)}

// ---------------------------------------------------------------------------
// Threefry-2x32 (JAX partitionable mode) — validated bit-exact (rel_err 7e-8)
// ---------------------------------------------------------------------------
__host__ __device__ __forceinline__ uint32_t rotl32(uint32_t x, int r) {
#ifdef __CUDA_ARCH__
    return __funnelshift_l(x, x, r);
#else
    return (x << r) | (x >> (32 - r));
#endif
}

__host__ __device__ __forceinline__ void threefry2x32(
    uint32_t k0, uint32_t k1, uint32_t x0, uint32_t x1,
    uint32_t& o0, uint32_t& o1)
{
    uint32_t ks2 = k0 ^ k1 ^ 0x1BD11BDAu;
    x0 += k0; x1 += k1;
#define TF_R(r) { x0 += x1; x1 = rotl32(x1, r); x1 ^= x0; }
    TF_R(13) TF_R(15) TF_R(26) TF_R(6)
    x0 += k1;  x1 += ks2 + 1u;
    TF_R(17) TF_R(29) TF_R(16) TF_R(24)
    x0 += ks2; x1 += k0 + 2u;
    TF_R(13) TF_R(15) TF_R(26) TF_R(6)
    x0 += k0;  x1 += k1 + 3u;
    TF_R(17) TF_R(29) TF_R(16) TF_R(24)
    x0 += k1;  x1 += ks2 + 4u;
    TF_R(13) TF_R(15) TF_R(26) TF_R(6)
    x0 += ks2; x1 += k0 + 5u;
#undef TF_R
    o0 = x0; o1 = x1;
}

__device__ __forceinline__ uint32_t tf_bits(uint32_t k0, uint32_t k1, uint32_t i) {
    uint32_t a, b;
    threefry2x32(k0, k1, 0u, i, a, b);
    return a ^ b;
}

__device__ __forceinline__ float bits_to_u01(uint32_t bits) {
    return __uint_as_float((bits >> 9) | 0x3f800000u) - 1.0f;
}

// ---------------------------------------------------------------------------
// CSR build: zero -> histogram -> 2-level exclusive scan -> scatter(+edge RNG)
// ---------------------------------------------------------------------------
__global__ void __launch_bounds__(256)
k_zero()
{
    unsigned i = blockIdx.x * blockDim.x + threadIdx.x;
    if (i < NNODES) g_deg[i] = 0u;
}

__global__ void __launch_bounds__(256)
k_hist(const int* __restrict__ rows)
{
    unsigned e = blockIdx.x * blockDim.x + threadIdx.x;
    if (e >= NNZ_E) return;
    atomicAdd(&g_deg[rows[e]], 1u);
}

// per-block exclusive scan over 1024 elems (256 threads x 4)
__global__ void __launch_bounds__(256)
k_scan1()
{
    __shared__ unsigned warp_sums[8];
    unsigned b = blockIdx.x;
    unsigned base = b * SCAN_BLK + threadIdx.x * 4u;
    unsigned v[4];
#pragma unroll
    for (int i = 0; i < 4; i++) {
        unsigned idx = base + i;
        v[i] = (idx < NNODES) ? g_deg[idx] : 0u;
    }
    unsigned tsum = v[0] + v[1] + v[2] + v[3];
    unsigned lane = threadIdx.x & 31u, wid = threadIdx.x >> 5;
    unsigned x = tsum;  // inclusive warp scan
#pragma unroll
    for (int o = 1; o < 32; o <<= 1) {
        unsigned y = __shfl_up_sync(0xFFFFFFFFu, x, o);
        if (lane >= (unsigned)o) x += y;
    }
    if (lane == 31) warp_sums[wid] = x;
    __syncthreads();
    if (wid == 0) {
        unsigned s = (lane < 8) ? warp_sums[lane] : 0u;
#pragma unroll
        for (int o = 1; o < 8; o <<= 1) {
            unsigned y = __shfl_up_sync(0xFFFFFFFFu, s, o);
            if (lane >= (unsigned)o) s += y;
        }
        if (lane < 8) warp_sums[lane] = s;  // inclusive over warps
    }
    __syncthreads();
    unsigned warp_off = (wid > 0) ? warp_sums[wid - 1] : 0u;
    unsigned run = warp_off + (x - tsum);   // thread-exclusive prefix
#pragma unroll
    for (int i = 0; i < 4; i++) {
        unsigned idx = base + i;
        if (idx < NNODES) g_rowptr[idx] = run;
        run += v[i];
    }
    if (threadIdx.x == 255) g_bsum[b] = warp_sums[7];  // block total
}

// single-block exclusive scan of block sums (NBLK = 293 <= 512)
__global__ void __launch_bounds__(512)
k_scan2()
{
    __shared__ unsigned sm[512];
    unsigned t = threadIdx.x;
    sm[t] = (t < NBLK) ? g_bsum[t] : 0u;
    __syncthreads();
#pragma unroll
    for (int o = 1; o < 512; o <<= 1) {
        unsigned y = (t >= (unsigned)o) ? sm[t - o] : 0u;
        __syncthreads();
        sm[t] += y;
        __syncthreads();
    }
    if (t < NBLK) g_bsum[t] = (t == 0) ? 0u : sm[t - 1];  // exclusive
}

__global__ void __launch_bounds__(256)
k_scan3()
{
    unsigned i = blockIdx.x * blockDim.x + threadIdx.x;
    if (i < NNODES) {
        g_rowptr[i] += g_bsum[i >> 10];
        g_deg[i] = 0u;                     // reuse as scatter cursor
    }
    if (i == 0) g_rowptr[NNODES] = NNZ_E;
}

// scatter + ALL-HOP edge dropout RNG; writes CSR-ordered {w0,w1,w2,col}
__global__ void __launch_bounds__(256)
k_scatter(const int* __restrict__ rows, const int* __restrict__ cols,
          const float* __restrict__ vals,
          uint32_t ka0, uint32_t ka1, uint32_t kb0, uint32_t kb1,
          uint32_t kc0, uint32_t kc1)
{
    unsigned e = blockIdx.x * blockDim.x + threadIdx.x;
    if (e >= NNZ_E) return;
    int r = rows[e];
    float v2 = vals[e] * 2.0f;
    float u0 = bits_to_u01(tf_bits(ka0, ka1, e));
    float u1 = bits_to_u01(tf_bits(kb0, kb1, e));
    float u2 = bits_to_u01(tf_bits(kc0, kc1, e));
    float4 ew;
    ew.x = (u0 >= 0.5f) ? v2 : 0.0f;
    ew.y = (u1 >= 0.5f) ? v2 : 0.0f;
    ew.z = (u2 >= 0.5f) ? v2 : 0.0f;
    ew.w = __int_as_float(cols[e]);
    unsigned pos = g_rowptr[r] + atomicAdd(&g_deg[r], 1u);
    g_ew3[pos] = ew;
}

// ---------------------------------------------------------------------------
// Fused SpMM + message dropout. ONE warp per row, float2 per lane (256B
// gathers). Unroll-4: 4 independent broadcast edge loads, then 4 independent
// gathers -> MLP ~4-5 instead of 2.
// ---------------------------------------------------------------------------
template <int HOP>
__global__ void __launch_bounds__(256)
k_spmm_fused(const float* __restrict__ ue, const float* __restrict__ ie,
             float* __restrict__ out, uint32_t km0, uint32_t km1)
{
    unsigned r = (blockIdx.x * blockDim.x + threadIdx.x) >> 5;  // row
    if (r >= NNODES) return;
    unsigned lane = threadIdx.x & 31u;

    unsigned start = g_rowptr[r];
    unsigned end   = g_rowptr[r + 1];

    float2 acc = make_float2(0.f, 0.f);
    const float* src_base = out + (size_t)HOP * DIM;   // when HOP>0

    auto wsel = [](const float4& e) {
        return (HOP == 0) ? e.x : (HOP == 1) ? e.y : e.z;
    };
    auto srow_of = [&](int c) -> const float* {
        if (HOP == 0)
            return (c < NUSERS) ? (ue + (size_t)c * DIM)
                                : (ie + (size_t)(c - NUSERS) * DIM);
        return src_base + (size_t)c * ROWSTRIDE;
    };

    const float4 z4 = make_float4(0.f, 0.f, 0.f, 0.f);
    for (unsigned p = start; p < end; p += 4u) {
        // 4 independent broadcast loads (predicated; all lanes same address)
        float4 e0 = g_ew3[p];
        float4 e1 = (p + 1u < end) ? g_ew3[p + 1u] : z4;
        float4 e2 = (p + 2u < end) ? g_ew3[p + 2u] : z4;
        float4 e3 = (p + 3u < end) ? g_ew3[p + 3u] : z4;
        float w0 = wsel(e0), w1 = wsel(e1), w2 = wsel(e2), w3 = wsel(e3);
        // 4 independent gathers
        float2 s0 = make_float2(0.f, 0.f), s1 = s0, s2 = s0, s3 = s0;
        if (w0 != 0.f) s0 = *reinterpret_cast<const float2*>(srow_of(__float_as_int(e0.w)) + lane * 2u);
        if (w1 != 0.f) s1 = *reinterpret_cast<const float2*>(srow_of(__float_as_int(e1.w)) + lane * 2u);
        if (w2 != 0.f) s2 = *reinterpret_cast<const float2*>(srow_of(__float_as_int(e2.w)) + lane * 2u);
        if (w3 != 0.f) s3 = *reinterpret_cast<const float2*>(srow_of(__float_as_int(e3.w)) + lane * 2u);
        acc.x += w0 * s0.x + w1 * s1.x + w2 * s2.x + w3 * s3.x;
        acc.y += w0 * s0.y + w1 * s1.y + w2 * s2.y + w3 * s3.y;
    }

    // message dropout epilogue: elements j, j+1 (two ciphers per lane)
    unsigned j = r * 64u + lane * 2u;
    uint32_t a0, b0, a1, b1;
    threefry2x32(km0, km1, 0u, j,      a0, b0);
    threefry2x32(km0, km1, 0u, j + 1u, a1, b1);
    float u0 = bits_to_u01(a0 ^ b0);
    float u1 = bits_to_u01(a1 ^ b1);

    float2 res;
    res.x = (u0 < 0.9f) ? acc.x * INV_MESS_KEEP : 0.0f;
    res.y = (u1 < 0.9f) ? acc.y * INV_MESS_KEEP : 0.0f;

    float* orow = out + (size_t)r * ROWSTRIDE;
    *reinterpret_cast<float2*>(orow + (size_t)(HOP + 1) * DIM + lane * 2u) = res;

    if (HOP == 0) {
        // emit level-0 copy (row r of concat(ue, ie))
        const float* erow = (r < NUSERS) ? (ue + (size_t)r * DIM)
                                         : (ie + (size_t)(r - NUSERS) * DIM);
        float2 e0 = *reinterpret_cast<const float2*>(erow + lane * 2u);
        *reinterpret_cast<float2*>(orow + lane * 2u) = e0;
    }
}

// ---------------------------------------------------------------------------
// Launch
// ---------------------------------------------------------------------------
extern "C" void kernel_launch(void* const* d_in, const int* in_sizes, int n_in,
                              void* d_out, int out_size)
{
    const float* ue = nullptr; const float* ie = nullptr;
    const float* vals = nullptr; const int* rows = nullptr; const int* cols = nullptr;
    int nnz_seen = 0;
    for (int i = 0; i < n_in; i++) {
        if (in_sizes[i] == NUSERS * DIM)      ue = (const float*)d_in[i];
        else if (in_sizes[i] == NITEMS * DIM) ie = (const float*)d_in[i];
        else if (in_sizes[i] == NNZ_E) {
            if (nnz_seen == 0)      vals = (const float*)d_in[i];
            else if (nnz_seen == 1) rows = (const int*)d_in[i];
            else                    cols = (const int*)d_in[i];
            nnz_seen++;
        }
    }
    float* out = (float*)d_out;

    // JAX key derivation (validated): base=(0,42); hk=cipher(base,(0,hop));
    // ke=cipher(hk,(0,0)), km=cipher(hk,(0,1))
    uint32_t ke0[NHOPS], ke1[NHOPS], km0[NHOPS], km1[NHOPS];
    for (int h = 0; h < NHOPS; h++) {
        uint32_t h0, h1;
        threefry2x32(0u, 42u, 0u, (uint32_t)h, h0, h1);
        threefry2x32(h0, h1, 0u, 0u, ke0[h], ke1[h]);
        threefry2x32(h0, h1, 0u, 1u, km0[h], km1[h]);
    }

    const int TB = 256;
    unsigned gb_node = (NNODES + TB - 1) / TB;
    unsigned gb_edge = (NNZ_E + TB - 1) / TB;
    unsigned gb_fuse = ((unsigned)NNODES * 32u + TB - 1) / TB;  // 1 warp/row

    k_zero<<<gb_node, TB>>>();
    k_hist<<<gb_edge, TB>>>(rows);
    k_scan1<<<NBLK, TB>>>();
    k_scan2<<<1, 512>>>();
    k_scan3<<<gb_node, TB>>>();
    k_scatter<<<gb_edge, TB>>>(rows, cols, vals,
                               ke0[0], ke1[0], ke0[1], ke1[1], ke0[2], ke1[2]);

    k_spmm_fused<0><<<gb_fuse, TB>>>(ue, ie, out, km0[0], km1[0]);
    k_spmm_fused<1><<<gb_fuse, TB>>>(ue, ie, out, km0[1], km1[1]);
    k_spmm_fused<2><<<gb_fuse, TB>>>(ue, ie, out, km0[2], km1[2]);
}

// round 8
// speedup vs baseline: 1.6607x; 1.0623x over previous
#include <cuda_runtime.h>
#include <cstdint>

#define NUSERS 100000
#define NITEMS 200000
#define NNODES 300000
#define DIM 64
#define ROWSTRIDE 256            // LEVELS * DIM
#define NNZ_E 1200000
#define NHOPS 3
#define INV_MESS_KEEP 1.1111112f // fp32(1/0.9)

#define SCAN_BLK 1024
#define NBLK ((NNODES + SCAN_BLK - 1) / SCAN_BLK)   // 293

// Scratch (__device__ globals; no allocations allowed). ~21 MB total.
__device__ unsigned g_deg[NNODES];        // degree histogram, then scatter cursor
__device__ unsigned g_rowptr[NNODES + 1]; // CSR row pointers
__device__ unsigned g_bsum[NBLK];         // scan block sums
__device__ float4   g_ew3[NNZ_E];         // CSR-ordered {w_hop0, w_hop1, w_hop2, bitcast(col)}

// ---------------------------------------------------------------------------
// Threefry-2x32 (JAX partitionable mode) — validated bit-exact (rel_err 7e-8)
// ---------------------------------------------------------------------------
__host__ __device__ __forceinline__ uint32_t rotl32(uint32_t x, int r) {
#ifdef __CUDA_ARCH__
    return __funnelshift_l(x, x, r);
#else
    return (x << r) | (x >> (32 - r));
#endif
}

__host__ __device__ __forceinline__ void threefry2x32(
    uint32_t k0, uint32_t k1, uint32_t x0, uint32_t x1,
    uint32_t& o0, uint32_t& o1)
{
    uint32_t ks2 = k0 ^ k1 ^ 0x1BD11BDAu;
    x0 += k0; x1 += k1;
#define TF_R(r) { x0 += x1; x1 = rotl32(x1, r); x1 ^= x0; }
    TF_R(13) TF_R(15) TF_R(26) TF_R(6)
    x0 += k1;  x1 += ks2 + 1u;
    TF_R(17) TF_R(29) TF_R(16) TF_R(24)
    x0 += ks2; x1 += k0 + 2u;
    TF_R(13) TF_R(15) TF_R(26) TF_R(6)
    x0 += k0;  x1 += k1 + 3u;
    TF_R(17) TF_R(29) TF_R(16) TF_R(24)
    x0 += k1;  x1 += ks2 + 4u;
    TF_R(13) TF_R(15) TF_R(26) TF_R(6)
    x0 += ks2; x1 += k0 + 5u;
#undef TF_R
    o0 = x0; o1 = x1;
}

__device__ __forceinline__ uint32_t tf_bits(uint32_t k0, uint32_t k1, uint32_t i) {
    uint32_t a, b;
    threefry2x32(k0, k1, 0u, i, a, b);
    return a ^ b;
}

__device__ __forceinline__ float bits_to_u01(uint32_t bits) {
    return __uint_as_float((bits >> 9) | 0x3f800000u) - 1.0f;
}

// ---------------------------------------------------------------------------
// CSR build: zero -> histogram -> 2-level exclusive scan -> scatter(+edge RNG)
// ---------------------------------------------------------------------------
__global__ void __launch_bounds__(256)
k_zero()
{
    unsigned i = blockIdx.x * blockDim.x + threadIdx.x;
    if (i < NNODES) g_deg[i] = 0u;
}

__global__ void __launch_bounds__(256)
k_hist(const int* __restrict__ rows)
{
    unsigned e = blockIdx.x * blockDim.x + threadIdx.x;
    if (e >= NNZ_E) return;
    atomicAdd(&g_deg[rows[e]], 1u);
}

// per-block exclusive scan over 1024 elems (256 threads x 4)
__global__ void __launch_bounds__(256)
k_scan1()
{
    __shared__ unsigned warp_sums[8];
    unsigned b = blockIdx.x;
    unsigned base = b * SCAN_BLK + threadIdx.x * 4u;
    unsigned v[4];
#pragma unroll
    for (int i = 0; i < 4; i++) {
        unsigned idx = base + i;
        v[i] = (idx < NNODES) ? g_deg[idx] : 0u;
    }
    unsigned tsum = v[0] + v[1] + v[2] + v[3];
    unsigned lane = threadIdx.x & 31u, wid = threadIdx.x >> 5;
    unsigned x = tsum;  // inclusive warp scan
#pragma unroll
    for (int o = 1; o < 32; o <<= 1) {
        unsigned y = __shfl_up_sync(0xFFFFFFFFu, x, o);
        if (lane >= (unsigned)o) x += y;
    }
    if (lane == 31) warp_sums[wid] = x;
    __syncthreads();
    if (wid == 0) {
        unsigned s = (lane < 8) ? warp_sums[lane] : 0u;
#pragma unroll
        for (int o = 1; o < 8; o <<= 1) {
            unsigned y = __shfl_up_sync(0xFFFFFFFFu, s, o);
            if (lane >= (unsigned)o) s += y;
        }
        if (lane < 8) warp_sums[lane] = s;  // inclusive over warps
    }
    __syncthreads();
    unsigned warp_off = (wid > 0) ? warp_sums[wid - 1] : 0u;
    unsigned run = warp_off + (x - tsum);   // thread-exclusive prefix
#pragma unroll
    for (int i = 0; i < 4; i++) {
        unsigned idx = base + i;
        if (idx < NNODES) g_rowptr[idx] = run;
        run += v[i];
    }
    if (threadIdx.x == 255) g_bsum[b] = warp_sums[7];  // block total
}

// single-block exclusive scan of block sums (NBLK = 293 <= 512)
__global__ void __launch_bounds__(512)
k_scan2()
{
    __shared__ unsigned sm[512];
    unsigned t = threadIdx.x;
    sm[t] = (t < NBLK) ? g_bsum[t] : 0u;
    __syncthreads();
#pragma unroll
    for (int o = 1; o < 512; o <<= 1) {
        unsigned y = (t >= (unsigned)o) ? sm[t - o] : 0u;
        __syncthreads();
        sm[t] += y;
        __syncthreads();
    }
    if (t < NBLK) g_bsum[t] = (t == 0) ? 0u : sm[t - 1];  // exclusive
}

__global__ void __launch_bounds__(256)
k_scan3()
{
    unsigned i = blockIdx.x * blockDim.x + threadIdx.x;
    if (i < NNODES) {
        g_rowptr[i] += g_bsum[i >> 10];
        g_deg[i] = 0u;                     // reuse as scatter cursor
    }
    if (i == 0) g_rowptr[NNODES] = NNZ_E;
}

// scatter + ALL-HOP edge dropout RNG; writes CSR-ordered {w0,w1,w2,col}
__global__ void __launch_bounds__(256)
k_scatter(const int* __restrict__ rows, const int* __restrict__ cols,
          const float* __restrict__ vals,
          uint32_t ka0, uint32_t ka1, uint32_t kb0, uint32_t kb1,
          uint32_t kc0, uint32_t kc1)
{
    unsigned e = blockIdx.x * blockDim.x + threadIdx.x;
    if (e >= NNZ_E) return;
    int r = rows[e];
    float v2 = vals[e] * 2.0f;
    float u0 = bits_to_u01(tf_bits(ka0, ka1, e));
    float u1 = bits_to_u01(tf_bits(kb0, kb1, e));
    float u2 = bits_to_u01(tf_bits(kc0, kc1, e));
    float4 ew;
    ew.x = (u0 >= 0.5f) ? v2 : 0.0f;
    ew.y = (u1 >= 0.5f) ? v2 : 0.0f;
    ew.z = (u2 >= 0.5f) ? v2 : 0.0f;
    ew.w = __int_as_float(cols[e]);
    unsigned pos = g_rowptr[r] + atomicAdd(&g_deg[r], 1u);
    g_ew3[pos] = ew;
}

// ---------------------------------------------------------------------------
// Fused SpMM + message dropout. ONE warp per row, float2 per lane.
// The two message-dropout ciphers are computed FIRST, so their ~150 cycles
// of ALU work issue while the rowptr/edge/gather loads are in flight
// (intra-warp ALU/mem overlap instead of cross-warp only).
// ---------------------------------------------------------------------------
template <int HOP>
__global__ void __launch_bounds__(256)
k_spmm_fused(const float* __restrict__ ue, const float* __restrict__ ie,
             float* __restrict__ out, uint32_t km0, uint32_t km1)
{
    unsigned r = (blockIdx.x * blockDim.x + threadIdx.x) >> 5;  // row
    if (r >= NNODES) return;
    unsigned lane = threadIdx.x & 31u;

    // issue rowptr loads immediately (scoreboarded)
    unsigned start = __ldg(&g_rowptr[r]);
    unsigned end   = __ldg(&g_rowptr[r + 1]);

    // --- hoisted message-dropout RNG: pure ALU, independent of all loads ---
    unsigned j = r * 64u + lane * 2u;
    uint32_t a0, b0, a1, b1;
    threefry2x32(km0, km1, 0u, j,      a0, b0);
    threefry2x32(km0, km1, 0u, j + 1u, a1, b1);
    float u0 = bits_to_u01(a0 ^ b0);
    float u1 = bits_to_u01(a1 ^ b1);
    float keep0 = (u0 < 0.9f) ? INV_MESS_KEEP : 0.0f;
    float keep1 = (u1 < 0.9f) ? INV_MESS_KEEP : 0.0f;

    float2 acc = make_float2(0.f, 0.f);
    const float* src_base = out + (size_t)HOP * DIM;   // when HOP>0

    auto wsel = [](const float4& e) {
        return (HOP == 0) ? e.x : (HOP == 1) ? e.y : e.z;
    };
    auto srow_of = [&](int c) -> const float* {
        if (HOP == 0)
            return (c < NUSERS) ? (ue + (size_t)c * DIM)
                                : (ie + (size_t)(c - NUSERS) * DIM);
        return src_base + (size_t)c * ROWSTRIDE;
    };

    const float4 z4 = make_float4(0.f, 0.f, 0.f, 0.f);
    for (unsigned p = start; p < end; p += 4u) {
        // 4 independent broadcast loads (predicated; all lanes same address)
        float4 e0 = g_ew3[p];
        float4 e1 = (p + 1u < end) ? g_ew3[p + 1u] : z4;
        float4 e2 = (p + 2u < end) ? g_ew3[p + 2u] : z4;
        float4 e3 = (p + 3u < end) ? g_ew3[p + 3u] : z4;
        float w0 = wsel(e0), w1 = wsel(e1), w2 = wsel(e2), w3 = wsel(e3);
        // 4 independent gathers
        float2 s0 = make_float2(0.f, 0.f), s1 = s0, s2 = s0, s3 = s0;
        if (w0 != 0.f) s0 = *reinterpret_cast<const float2*>(srow_of(__float_as_int(e0.w)) + lane * 2u);
        if (w1 != 0.f) s1 = *reinterpret_cast<const float2*>(srow_of(__float_as_int(e1.w)) + lane * 2u);
        if (w2 != 0.f) s2 = *reinterpret_cast<const float2*>(srow_of(__float_as_int(e2.w)) + lane * 2u);
        if (w3 != 0.f) s3 = *reinterpret_cast<const float2*>(srow_of(__float_as_int(e3.w)) + lane * 2u);
        acc.x += w0 * s0.x + w1 * s1.x + w2 * s2.x + w3 * s3.x;
        acc.y += w0 * s0.y + w1 * s1.y + w2 * s2.y + w3 * s3.y;
    }

    // tiny epilogue: apply precomputed keep factors and store
    float2 res;
    res.x = acc.x * keep0;
    res.y = acc.y * keep1;

    float* orow = out + (size_t)r * ROWSTRIDE;
    *reinterpret_cast<float2*>(orow + (size_t)(HOP + 1) * DIM + lane * 2u) = res;

    if (HOP == 0) {
        // emit level-0 copy (row r of concat(ue, ie))
        const float* erow = (r < NUSERS) ? (ue + (size_t)r * DIM)
                                         : (ie + (size_t)(r - NUSERS) * DIM);
        float2 e0 = *reinterpret_cast<const float2*>(erow + lane * 2u);
        *reinterpret_cast<float2*>(orow + lane * 2u) = e0;
    }
}

// ---------------------------------------------------------------------------
// Launch
// ---------------------------------------------------------------------------
extern "C" void kernel_launch(void* const* d_in, const int* in_sizes, int n_in,
                              void* d_out, int out_size)
{
    const float* ue = nullptr; const float* ie = nullptr;
    const float* vals = nullptr; const int* rows = nullptr; const int* cols = nullptr;
    int nnz_seen = 0;
    for (int i = 0; i < n_in; i++) {
        if (in_sizes[i] == NUSERS * DIM)      ue = (const float*)d_in[i];
        else if (in_sizes[i] == NITEMS * DIM) ie = (const float*)d_in[i];
        else if (in_sizes[i] == NNZ_E) {
            if (nnz_seen == 0)      vals = (const float*)d_in[i];
            else if (nnz_seen == 1) rows = (const int*)d_in[i];
            else                    cols = (const int*)d_in[i];
            nnz_seen++;
        }
    }
    float* out = (float*)d_out;

    // JAX key derivation (validated): base=(0,42); hk=cipher(base,(0,hop));
    // ke=cipher(hk,(0,0)), km=cipher(hk,(0,1))
    uint32_t ke0[NHOPS], ke1[NHOPS], km0[NHOPS], km1[NHOPS];
    for (int h = 0; h < NHOPS; h++) {
        uint32_t h0, h1;
        threefry2x32(0u, 42u, 0u, (uint32_t)h, h0, h1);
        threefry2x32(h0, h1, 0u, 0u, ke0[h], ke1[h]);
        threefry2x32(h0, h1, 0u, 1u, km0[h], km1[h]);
    }

    const int TB = 256;
    unsigned gb_node = (NNODES + TB - 1) / TB;
    unsigned gb_edge = (NNZ_E + TB - 1) / TB;
    unsigned gb_fuse = ((unsigned)NNODES * 32u + TB - 1) / TB;  // 1 warp/row

    k_zero<<<gb_node, TB>>>();
    k_hist<<<gb_edge, TB>>>(rows);
    k_scan1<<<NBLK, TB>>>();
    k_scan2<<<1, 512>>>();
    k_scan3<<<gb_node, TB>>>();
    k_scatter<<<gb_edge, TB>>>(rows, cols, vals,
                               ke0[0], ke1[0], ke0[1], ke1[1], ke0[2], ke1[2]);

    k_spmm_fused<0><<<gb_fuse, TB>>>(ue, ie, out, km0[0], km1[0]);
    k_spmm_fused<1><<<gb_fuse, TB>>>(ue, ie, out, km0[1], km1[1]);
    k_spmm_fused<2><<<gb_fuse, TB>>>(ue, ie, out, km0[2], km1[2]);
}